// round 6
// baseline (speedup 1.0000x reference)
#include <cuda_runtime.h>

// B=128, N=1024. out[b,k] = a[b,j] - a[b,i], strict upper triangle (j>i),
// row-major pair order. Row i (len 1023-i) starts at off(i) = i*(2047-i)/2.
//
// Decomposition: one ROW-PAIR per warp: warp handles row p (len 1023-p) and
// row 1022-p (len p+1) -> exactly 1024 outputs per warp, perfectly balanced,
// row index known from the schedule (zero per-element index math).

constexpr int N_ELEM  = 1024;
constexpr int M_PAIRS = N_ELEM * (N_ELEM - 1) / 2;   // 523776
constexpr int THREADS = 256;                          // 8 warps -> 8 pairs/block
constexpr int PITCH   = N_ELEM + 4;                   // 16B-aligned copy pitch

__device__ __forceinline__ int row_off(int i) {
    return (i * (2047 - i)) >> 1;                     // exact (product even)
}

// Process one full row with one warp. sh = shifted smem copies.
__device__ __forceinline__ void warp_row(int i, const float* __restrict__ sh,
                                         float* __restrict__ outb, int lane) {
    const int start = row_off(i);
    const int len   = 1023 - i;
    const int end   = start + len;
    const float ai  = sh[i];                          // broadcast LDS

    const int astart = (start + 3) & ~3;              // aligned region start
    const int aend   = end & ~3;                      // aligned region end

    // Head scalars: [start, min(astart,end))  (<=3 lanes)
    const int head_n = min(astart, end) - start;
    if (lane < head_n)
        outb[start + lane] = sh[i + 1 + lane] - ai;

    // Tail scalars: [max(aend,astart), end)  (<=3 lanes; empty if negative)
    const int tstart = max(aend, astart);
    const int tail_n = end - tstart;
    if (lane < tail_n)
        outb[tstart + lane] = sh[i + 1 + (tstart - start) + lane] - ai;

    // Aligned bulk: n4 float4s, warp-strided. One conflict-free LDS.128 from
    // the shifted copy matching this row's alignment + 4 FADD + STG.128.
    int n4 = (aend - astart) >> 2;
    if (n4 < 0) n4 = 0;
    const int jbase = i + 1 + (astart - start);       // j at aligned start
    const int r     = jbase & 3;                      // uniform per row
    const float* __restrict__ src = sh + r * PITCH + (jbase - r);
    float* __restrict__ dst = outb + astart;

    for (int q = lane; q < n4; q += 32) {
        const float4 v = *reinterpret_cast<const float4*>(src + (q << 2));
        *reinterpret_cast<float4*>(dst + (q << 2)) =
            make_float4(v.x - ai, v.y - ai, v.z - ai, v.w - ai);
    }
}

__global__ __launch_bounds__(THREADS)
void relpos_kernel(const float* __restrict__ in, float* __restrict__ out) {
    // 4 shifted copies: sh[r*PITCH + m] = a[m + r]
    __shared__ float sh[4 * PITCH];

    const int b = blockIdx.y;
    const float* a = in + (size_t)b * N_ELEM;

    // Stage input + build shifted copies (one float4 per thread).
    {
        const float4 v = reinterpret_cast<const float4*>(a)[threadIdx.x];
        const int idx = threadIdx.x * 4;
        const float vv[4] = {v.x, v.y, v.z, v.w};
        #pragma unroll
        for (int e = 0; e < 4; e++) {
            const int x = idx + e;
            const float val = vv[e];
            #pragma unroll
            for (int r = 0; r < 4; r++) {
                const int m = x - r;
                if (m >= 0) sh[r * PITCH + m] = val;
            }
        }
    }
    __syncthreads();

    float* outb = out + (size_t)b * M_PAIRS;
    const int warp = threadIdx.x >> 5;
    const int lane = threadIdx.x & 31;

    const int p = blockIdx.x * (THREADS / 32) + warp; // pair id, 0..511
    warp_row(p, sh, outb, lane);                      // long row (len 1023-p)
    if (p < 511)
        warp_row(1022 - p, sh, outb, lane);           // short partner (len p+1)
}

extern "C" void kernel_launch(void* const* d_in, const int* in_sizes, int n_in,
                              void* d_out, int out_size) {
    const float* in = (const float*)d_in[0];
    float* out = (float*)d_out;
    const int B = in_sizes[0] / N_ELEM;               // 128

    dim3 grid(512 / (THREADS / 32), B);               // (64, 128)
    relpos_kernel<<<grid, THREADS>>>(in, out);
}

// round 7
// speedup vs baseline: 1.5206x; 1.5206x over previous
#include <cuda_runtime.h>

// B=128, N=1024. out[b,k] = a[b,j] - a[b,i], strict upper triangle (j>i),
// row-major pair order. Row i (len 1023-i) starts at off(i) = i*(2047-i)/2.
//
// One ROW-PAIR per warp: warp w handles row p (len 1023-p) and row 1022-p
// (len p+1) -> exactly 1024 outputs/warp. Row index comes from the schedule
// (no per-element index math). Bulk work is fully unrolled + predicated so
// all LDS.128 issue back-to-back (MLP ~12) before any dependent store.

constexpr int N_ELEM  = 1024;
constexpr int M_PAIRS = N_ELEM * (N_ELEM - 1) / 2;   // 523776
constexpr int THREADS = 256;                          // 8 warps = 8 pairs/block
constexpr int PITCH   = N_ELEM + 4;                   // 16B-aligned copy pitch
constexpr int UL      = 8;                            // long-row unroll (n4 <= 255)
constexpr int US      = 4;                            // short-row unroll (n4 <= 128)

__device__ __forceinline__ int row_off(int i) {
    return (i * (2047 - i)) >> 1;                     // exact (product even)
}

struct RowCtx {
    const float* src;   // aligned smem source (shifted copy)
    float* dst;         // aligned global dest
    int n4;             // aligned float4 count
    float ai;
};

__device__ __forceinline__ RowCtx row_setup(int i, const float* __restrict__ sh,
                                            float* __restrict__ outb, int lane) {
    const int start = row_off(i);
    const int len   = 1023 - i;
    const int end   = start + len;
    const float ai  = sh[i];                          // broadcast LDS

    const int astart = (start + 3) & ~3;
    const int aend   = end & ~3;

    // Head scalars (<=3 lanes)
    const int head_n = min(astart, end) - start;
    if (lane < head_n)
        outb[start + lane] = sh[i + 1 + lane] - ai;

    // Tail scalars (<=3 lanes)
    const int tstart = max(aend, astart);
    const int tail_n = end - tstart;
    if (lane < tail_n)
        outb[tstart + lane] = sh[i + 1 + (tstart - start) + lane] - ai;

    int n4 = (aend - astart) >> 2;
    if (n4 < 0) n4 = 0;
    const int jbase = i + 1 + (astart - start);
    const int r     = jbase & 3;

    RowCtx c;
    c.src = sh + r * PITCH + (jbase - r);
    c.dst = outb + astart;
    c.n4  = n4;
    c.ai  = ai;
    return c;
}

__global__ __launch_bounds__(THREADS)
void relpos_kernel(const float* __restrict__ in, float* __restrict__ out) {
    // 4 shifted copies: sh[r*PITCH + m] = a[m + r]
    __shared__ float sh[4 * PITCH];

    const int b = blockIdx.y;
    const float* a = in + (size_t)b * N_ELEM;

    // Stage input + build shifted copies (one float4 per thread).
    {
        const float4 v = reinterpret_cast<const float4*>(a)[threadIdx.x];
        const int idx = threadIdx.x * 4;
        const float vv[4] = {v.x, v.y, v.z, v.w};
        #pragma unroll
        for (int e = 0; e < 4; e++) {
            const int x = idx + e;
            const float val = vv[e];
            #pragma unroll
            for (int r = 0; r < 4; r++) {
                const int m = x - r;
                if (m >= 0) sh[r * PITCH + m] = val;
            }
        }
    }
    __syncthreads();

    float* outb = out + (size_t)b * M_PAIRS;
    const int warp = threadIdx.x >> 5;
    const int lane = threadIdx.x & 31;

    const int p = blockIdx.x * (THREADS / 32) + warp; // pair id, 0..511
    const int iS = 1022 - p;
    const bool hasS = (p < 511);

    // Per-row setup (includes head/tail peel + ai broadcast).
    RowCtx L = row_setup(p, sh, outb, lane);
    RowCtx S;
    S.n4 = 0; S.ai = 0.f; S.src = sh; S.dst = outb;
    if (hasS) S = row_setup(iS, sh, outb, lane);

    // ---- Phase 1: issue ALL loads (predicated, back-to-back -> high MLP) ----
    float4 Lv[UL], Sv[US];
    #pragma unroll
    for (int u = 0; u < UL; u++) {
        const int q = lane + 32 * u;
        if (q < L.n4)
            Lv[u] = *reinterpret_cast<const float4*>(L.src + (q << 2));
    }
    #pragma unroll
    for (int u = 0; u < US; u++) {
        const int q = lane + 32 * u;
        if (q < S.n4)
            Sv[u] = *reinterpret_cast<const float4*>(S.src + (q << 2));
    }

    // ---- Phase 2: compute + store (stores flow out with deep MLP) ----
    #pragma unroll
    for (int u = 0; u < UL; u++) {
        const int q = lane + 32 * u;
        if (q < L.n4) {
            const float4 v = Lv[u];
            *reinterpret_cast<float4*>(L.dst + (q << 2)) =
                make_float4(v.x - L.ai, v.y - L.ai, v.z - L.ai, v.w - L.ai);
        }
    }
    #pragma unroll
    for (int u = 0; u < US; u++) {
        const int q = lane + 32 * u;
        if (q < S.n4) {
            const float4 v = Sv[u];
            *reinterpret_cast<float4*>(S.dst + (q << 2)) =
                make_float4(v.x - S.ai, v.y - S.ai, v.z - S.ai, v.w - S.ai);
        }
    }
}

extern "C" void kernel_launch(void* const* d_in, const int* in_sizes, int n_in,
                              void* d_out, int out_size) {
    const float* in = (const float*)d_in[0];
    float* out = (float*)d_out;
    const int B = in_sizes[0] / N_ELEM;               // 128

    dim3 grid(512 / (THREADS / 32), B);               // (64, 128)
    relpos_kernel<<<grid, THREADS>>>(in, out);
}